// round 12
// baseline (speedup 1.0000x reference)
#include <cuda_runtime.h>
#include <math.h>
#include <stdint.h>

#define NN 4096
#define CAP 512

// ---------------- device globals (allocation-free scratch) ----------------
__device__ __align__(16) signed char g_d8[NN];
__device__ __align__(16) unsigned g_list[(size_t)NN * CAP];  // entry: idx | (b&0xFF)<<16
__device__ int g_cnt[NN];
__device__ int g_nD;
__device__ unsigned long long g_triS, g_triE;
__device__ unsigned long long g_T1, g_T2, g_S, g_TA, g_TB;
__device__ unsigned g_done;

// zero append counters (replay-safe)
__global__ void k_zcnt() { g_cnt[blockIdx.x * 256 + threadIdx.x] = 0; }

static __device__ __forceinline__ void append_nz(int r, int c0, unsigned w) {
    unsigned nzm = ~__vcmpeq4(w, 0u);
    int nzc = __popc(nzm) >> 3;
    if (nzc == 0) return;
    int pos = atomicAdd(&g_cnt[r], nzc);
    #pragma unroll
    for (int t = 0; t < 4; t++) {
        if (nzm & (0xFFu << (8 * t))) {
            int b = (int)(w << (24 - 8 * t)) >> 24;
            if (pos < CAP)
                g_list[(size_t)r * CAP + pos] =
                    (unsigned)(c0 + t) | (((unsigned)b & 0xFFu) << 16);
            pos++;
        }
    }
}

// Fused: mod_adj + B = m + m^T nonzero extraction + diag + accumulator reset.
// hard = 1 <=> logit(p)+logit(u) > 0 <=> p + (u-1) > 0 (u-1 exact by Sterbenz).
__global__ void k_fuse(const float* __restrict__ ori, const float* __restrict__ cp,
                       const float* __restrict__ u, float* __restrict__ mod) {
    __shared__ unsigned m1w[32][9];
    __shared__ unsigned m2w[32][9];
    const int bx = blockIdx.x, by = blockIdx.y;
    if (bx < by) return;
    const int bi = by * 32, bj = bx * 32;
    const int tx = threadIdx.x;   // 0..7
    const int ty = threadIdx.y;   // 0..31
    const int tid = ty * 8 + tx;
    const bool diag = (bx == by);

    if (bx == 0 && by == 0 && tid == 0) {
        g_triS = 0ull; g_triE = 0ull; g_nD = 0; g_done = 0u;
        g_T1 = 0ull; g_T2 = 0ull; g_S = 0ull; g_TA = 0ull; g_TB = 0ull;
    }

    {
        size_t idx = ((size_t)(bi + ty) * NN + bj + tx * 4) >> 2;
        float4 o = __ldcs((const float4*)ori + idx);
        float4 c = __ldcs((const float4*)cp + idx);
        float4 w = __ldcs((const float4*)u + idx);
        float4 m;
        m.x = (c.x + (w.x - 1.0f) > 0.0f) ? -o.x : o.x;
        m.y = (c.y + (w.y - 1.0f) > 0.0f) ? -o.y : o.y;
        m.z = (c.z + (w.z - 1.0f) > 0.0f) ? -o.z : o.z;
        m.w = (c.w + (w.w - 1.0f) > 0.0f) ? -o.w : o.w;
        __stcs((float4*)mod + idx, m);
        m1w[ty][tx] = ((unsigned)(int)m.x & 0xFFu)
                    | (((unsigned)(int)m.y & 0xFFu) << 8)
                    | (((unsigned)(int)m.z & 0xFFu) << 16)
                    | (((unsigned)(int)m.w & 0xFFu) << 24);
    }
    if (!diag) {
        size_t idx = ((size_t)(bj + ty) * NN + bi + tx * 4) >> 2;
        float4 o = __ldcs((const float4*)ori + idx);
        float4 c = __ldcs((const float4*)cp + idx);
        float4 w = __ldcs((const float4*)u + idx);
        float4 m;
        m.x = (c.x + (w.x - 1.0f) > 0.0f) ? -o.x : o.x;
        m.y = (c.y + (w.y - 1.0f) > 0.0f) ? -o.y : o.y;
        m.z = (c.z + (w.z - 1.0f) > 0.0f) ? -o.z : o.z;
        m.w = (c.w + (w.w - 1.0f) > 0.0f) ? -o.w : o.w;
        __stcs((float4*)mod + idx, m);
        m2w[ty][tx] = ((unsigned)(int)m.x & 0xFFu)
                    | (((unsigned)(int)m.y & 0xFFu) << 8)
                    | (((unsigned)(int)m.z & 0xFFu) << 16)
                    | (((unsigned)(int)m.w & 0xFFu) << 24);
    }
    __syncthreads();
    {   // B tile1: rows bi+ty, cols bj+tx*4..+3
        unsigned w1 = m1w[ty][tx];
        unsigned out = 0;
        #pragma unroll
        for (int q = 0; q < 4; q++) {
            int a = (int)(w1 << (24 - 8 * q)) >> 24;
            unsigned wt = diag ? m1w[tx * 4 + q][ty >> 2] : m2w[tx * 4 + q][ty >> 2];
            int b = (int)(wt << (24 - 8 * (ty & 3))) >> 24;
            out |= ((unsigned)(a + b) & 0xFFu) << (8 * q);
        }
        append_nz(bi + ty, bj + tx * 4, out);
    }
    if (!diag) {  // B tile2: rows bj+ty, cols bi+tx*4..+3
        unsigned w1 = m2w[ty][tx];
        unsigned out = 0;
        #pragma unroll
        for (int q = 0; q < 4; q++) {
            int a = (int)(w1 << (24 - 8 * q)) >> 24;
            unsigned wt = m1w[tx * 4 + q][ty >> 2];
            int b = (int)(wt << (24 - 8 * (ty & 3))) >> 24;
            out |= ((unsigned)(a + b) & 0xFFu) << (8 * q);
        }
        append_nz(bj + ty, bi + tx * 4, out);
    }
    if (diag && tx == (ty >> 2)) {
        int d = (int)(m1w[ty][tx] << (24 - 8 * (ty & 3))) >> 24;
        g_d8[bi + ty] = (signed char)d;
    }
}

// Sparse traces + all per-row scalars + final balance (threadfence reduction).
__global__ void __launch_bounds__(256) k_tri(float* __restrict__ out, int out_size) {
    __shared__ signed char s_d[NN];          // 4 KB: full d vector
    __shared__ unsigned short s_be[NN];      // 8 KB: (B[j,i], E[j,i]) bytes
    __shared__ unsigned jl[CAP];             // 2 KB: own list
    __shared__ long long redS[8], redE[8];
    __shared__ int redI[32];
    const int j = blockIdx.x, tid = threadIdx.x, lane = tid & 31, wid = tid >> 5;

    ((uint4*)s_d)[tid] = ((const uint4*)g_d8)[tid];
    ((uint4*)s_be)[tid] = make_uint4(0, 0, 0, 0);
    ((uint4*)s_be)[tid + 256] = make_uint4(0, 0, 0, 0);
    const int cj = min(g_cnt[j], CAP);
    for (int t = tid; t < cj; t += 256) jl[t] = g_list[(size_t)j * CAP + t];
    __syncthreads();
    const int dj = (int)s_d[j];

    // scatter s_be + per-row scalar sums from own list
    int rB = 0, rBd = 0, rE = 0, cEf = 0;
    for (int t = tid; t < cj; t += 256) {
        unsigned e = jl[t];
        int i = (int)(e & 0xFFFFu);
        int b = (int)(e << 8) >> 24;
        int di = (int)s_d[i];
        int ei = di ? (abs(b - di) - 1) : abs(b);        // E[j,i] (uses d_i)
        s_be[i] = (unsigned short)(((unsigned)b & 0xFFu) | (((unsigned)ei & 0xFFu) << 8));
        rB += b; rBd += b * di; rE += ei;
        if (di) cEf += dj ? (abs(b - dj) - 1) : abs(b);  // E[i,j] (uses d_j), i in D
    }
    #pragma unroll
    for (int o = 16; o > 0; o >>= 1) {
        rB  += __shfl_down_sync(0xFFFFFFFFu, rB, o);
        rBd += __shfl_down_sync(0xFFFFFFFFu, rBd, o);
        rE  += __shfl_down_sync(0xFFFFFFFFu, rE, o);
        cEf += __shfl_down_sync(0xFFFFFFFFu, cEf, o);
    }
    if (lane == 0) { redI[wid] = rB; redI[8 + wid] = rBd; redI[16 + wid] = rE; redI[24 + wid] = cEf; }
    __syncthreads();

    int aS = 0, aE = 0;
    for (int kk = wid; kk < cj; kk += 8) {
        unsigned e = jl[kk];
        int k = (int)(e & 0xFFFFu);
        int bkj = (int)(e << 8) >> 24;
        int dk = (int)s_d[k];
        int ekj = dj ? (abs(bkj - dj) - 1) : abs(bkj);   // E[k,j]
        unsigned dkw = ((unsigned)dk & 0xFFu) * 0x00010001u;
        unsigned s1w = dk ? 0x00010001u : 0u;
        const int ck = min(__ldg(&g_cnt[k]), CAP);
        const uint4* lk = (const uint4*)(g_list + (size_t)k * CAP);
        int sk = 0, ek = 0;
        const int g4 = ck >> 2;
        for (int t = lane; t < g4; t += 32) {
            uint4 w4 = __ldg(&lk[t]);
            {
                unsigned bb = __byte_perm(w4.x, w4.y, 0x0602) & 0x00FF00FFu;
                unsigned ee = __vsubss4((int)__vabsss4((int)__vsubss4((int)bb, (int)dkw)), (int)s1w);
                unsigned be2 = __byte_perm(s_be[w4.x & 0xFFFFu], s_be[w4.y & 0xFFFFu], 0x5410);
                sk = __dp4a((int)bb, (int)be2, sk);
                ek = __dp4a((int)(ee << 8), (int)be2, ek);
            }
            {
                unsigned bb = __byte_perm(w4.z, w4.w, 0x0602) & 0x00FF00FFu;
                unsigned ee = __vsubss4((int)__vabsss4((int)__vsubss4((int)bb, (int)dkw)), (int)s1w);
                unsigned be2 = __byte_perm(s_be[w4.z & 0xFFFFu], s_be[w4.w & 0xFFFFu], 0x5410);
                sk = __dp4a((int)bb, (int)be2, sk);
                ek = __dp4a((int)(ee << 8), (int)be2, ek);
            }
        }
        // tail (ck & 3 entries, scalar)
        const unsigned* lks = (const unsigned*)lk;
        for (int t = (ck & ~3) + lane; t < ck; t += 32) {
            unsigned w = __ldg(lks + t);
            int i = (int)(w & 0xFFFFu);
            int b = (int)(w << 8) >> 24;
            int ei = dk ? (abs(b - dk) - 1) : abs(b);
            unsigned v = s_be[i];
            sk += b * (((int)(v << 24)) >> 24);
            ek += ei * (((int)(v << 16)) >> 24);
        }
        aS += bkj * sk;
        aE += ekj * ek;
    }
    #pragma unroll
    for (int o = 16; o > 0; o >>= 1) {
        aS += __shfl_down_sync(0xFFFFFFFFu, aS, o);
        aE += __shfl_down_sync(0xFFFFFFFFu, aE, o);
    }
    if (lane == 0) { redS[wid] = aS; redE[wid] = aE; }
    __syncthreads();
    if (tid == 0) {
        long long s = 0, t = 0;
        int RB = 0, RBD = 0, RE = 0, CEF = 0;
        #pragma unroll
        for (int w = 0; w < 8; w++) {
            s += redS[w]; t += redE[w];
            RB += redI[w]; RBD += redI[8 + w]; RE += redI[16 + w]; CEF += redI[24 + w];
        }
        atomicAdd(&g_triS, (unsigned long long)s);
        atomicAdd(&g_triE, (unsigned long long)t);
        atomicAdd(&g_T1, (unsigned long long)((long long)RBD * (long long)RB));
        atomicAdd(&g_TA, (unsigned long long)((long long)CEF * (long long)RE));
        if (dj != 0) {
            atomicAdd(&g_T2, (unsigned long long)((long long)dj * (long long)RB));
            atomicAdd(&g_S, (unsigned long long)(long long)dj);
            atomicAdd(&g_TB, (unsigned long long)(long long)RE);
            atomicAdd(&g_nD, 1);
        }
        __threadfence();
        unsigned prev = atomicAdd(&g_done, 1u);
        if (prev == (unsigned)(NN - 1)) {
            long long triS = (long long)atomicAdd(&g_triS, 0ull);
            long long triE = (long long)atomicAdd(&g_triE, 0ull);
            long long T1 = (long long)atomicAdd(&g_T1, 0ull);
            long long T2 = (long long)atomicAdd(&g_T2, 0ull);
            long long Sv = (long long)atomicAdd(&g_S, 0ull);
            long long TA = (long long)atomicAdd(&g_TA, 0ull);
            long long TB = (long long)atomicAdd(&g_TB, 0ull);
            long long nD = (long long)atomicAdd(&g_nD, 0);
            // tr(A^3)  = tr(B^3) - 3*T1 + 3*S*T2 - S^3
            // tr(|A|^3)= tr(E^3) + 3*TA + 3*|D|*TB + |D|^3
            long long tr3  = triS - 3 * T1 + 3 * Sv * T2 - Sv * Sv * Sv;
            long long tr3a = triE + 3 * TA + 3 * nD * TB + nD * nD * nD;
            out[out_size - 1] = (float)(0.5 * (1.0 + (double)tr3 / (double)tr3a));
        }
    }
}

// ---------------- launch ----------------
extern "C" void kernel_launch(void* const* d_in, const int* in_sizes, int n_in,
                              void* d_out, int out_size) {
    const float* ori = (const float*)d_in[0];
    const float* cp  = (const float*)d_in[1];
    const float* u   = (const float*)d_in[2];
    float* out = (float*)d_out;

    k_zcnt<<<NN / 256, 256>>>();
    k_fuse<<<dim3(128, 128), dim3(8, 32)>>>(ori, cp, u, out);
    k_tri<<<NN, 256>>>(out, out_size);
}

// round 13
// speedup vs baseline: 1.0945x; 1.0945x over previous
#include <cuda_runtime.h>
#include <math.h>
#include <stdint.h>

#define NN 4096
#define CAP 512
#define CAPG (CAP / 2)

// ---------------- device globals (allocation-free scratch) ----------------
__device__ __align__(16) signed char g_B8[(size_t)NN * NN];   // B = m + m^T
__device__ __align__(16) signed char g_d8[NN];
__device__ int g_nD;
__device__ __align__(16) uint2 g_list2[(size_t)NN * CAPG];    // 2 entries per uint2
__device__ int g_cnt[NN];
__device__ int g_rowsE[NN], g_colEf[NN];
__device__ unsigned long long g_triS, g_triE;
__device__ unsigned long long g_T1, g_T2, g_S, g_TA, g_TB;
__device__ unsigned g_done;

// Fused: mod_adj + B = m + m^T + diag + zeroing of accumulators.
// hard = 1 <=> logit(p)+logit(u) > 0 <=> p + (u-1) > 0 (u-1 exact by Sterbenz).
__global__ void k_fuse(const float* __restrict__ ori, const float* __restrict__ cp,
                       const float* __restrict__ u, float* __restrict__ mod) {
    __shared__ unsigned m1w[32][9];
    __shared__ unsigned m2w[32][9];
    const int bx = blockIdx.x, by = blockIdx.y;
    if (bx < by) return;
    const int bi = by * 32, bj = bx * 32;
    const int tx = threadIdx.x;   // 0..7
    const int ty = threadIdx.y;   // 0..31
    const int tid = ty * 8 + tx;
    const bool diag = (bx == by);

    if (diag && tid < 32) g_colEf[bi + tid] = 0;
    if (bx == 0 && by == 0 && tid == 0) {
        g_triS = 0ull; g_triE = 0ull; g_nD = 0; g_done = 0u;
        g_T1 = 0ull; g_T2 = 0ull; g_S = 0ull; g_TA = 0ull; g_TB = 0ull;
    }

    {
        size_t idx = ((size_t)(bi + ty) * NN + bj + tx * 4) >> 2;
        float4 o = __ldcs((const float4*)ori + idx);
        float4 c = __ldcs((const float4*)cp + idx);
        float4 w = __ldcs((const float4*)u + idx);
        float4 m;
        m.x = (c.x + (w.x - 1.0f) > 0.0f) ? -o.x : o.x;
        m.y = (c.y + (w.y - 1.0f) > 0.0f) ? -o.y : o.y;
        m.z = (c.z + (w.z - 1.0f) > 0.0f) ? -o.z : o.z;
        m.w = (c.w + (w.w - 1.0f) > 0.0f) ? -o.w : o.w;
        __stcs((float4*)mod + idx, m);
        m1w[ty][tx] = ((unsigned)(int)m.x & 0xFFu)
                    | (((unsigned)(int)m.y & 0xFFu) << 8)
                    | (((unsigned)(int)m.z & 0xFFu) << 16)
                    | (((unsigned)(int)m.w & 0xFFu) << 24);
    }
    if (!diag) {
        size_t idx = ((size_t)(bj + ty) * NN + bi + tx * 4) >> 2;
        float4 o = __ldcs((const float4*)ori + idx);
        float4 c = __ldcs((const float4*)cp + idx);
        float4 w = __ldcs((const float4*)u + idx);
        float4 m;
        m.x = (c.x + (w.x - 1.0f) > 0.0f) ? -o.x : o.x;
        m.y = (c.y + (w.y - 1.0f) > 0.0f) ? -o.y : o.y;
        m.z = (c.z + (w.z - 1.0f) > 0.0f) ? -o.z : o.z;
        m.w = (c.w + (w.w - 1.0f) > 0.0f) ? -o.w : o.w;
        __stcs((float4*)mod + idx, m);
        m2w[ty][tx] = ((unsigned)(int)m.x & 0xFFu)
                    | (((unsigned)(int)m.y & 0xFFu) << 8)
                    | (((unsigned)(int)m.z & 0xFFu) << 16)
                    | (((unsigned)(int)m.w & 0xFFu) << 24);
    }
    __syncthreads();
    {   // B tile1: rows bi+ty, cols bj+tx*4..+3
        unsigned w1 = m1w[ty][tx];
        unsigned out = 0;
        #pragma unroll
        for (int q = 0; q < 4; q++) {
            int a = (int)(w1 << (24 - 8 * q)) >> 24;
            unsigned wt = diag ? m1w[tx * 4 + q][ty >> 2] : m2w[tx * 4 + q][ty >> 2];
            int b = (int)(wt << (24 - 8 * (ty & 3))) >> 24;
            out |= ((unsigned)(a + b) & 0xFFu) << (8 * q);
        }
        *(unsigned*)(g_B8 + (size_t)(bi + ty) * NN + bj + tx * 4) = out;
    }
    if (!diag) {  // B tile2: rows bj+ty, cols bi+tx*4..+3
        unsigned w1 = m2w[ty][tx];
        unsigned out = 0;
        #pragma unroll
        for (int q = 0; q < 4; q++) {
            int a = (int)(w1 << (24 - 8 * q)) >> 24;
            unsigned wt = m1w[tx * 4 + q][ty >> 2];
            int b = (int)(wt << (24 - 8 * (ty & 3))) >> 24;
            out |= ((unsigned)(a + b) & 0xFFu) << (8 * q);
        }
        *(unsigned*)(g_B8 + (size_t)(bj + ty) * NN + bi + tx * 4) = out;
    }
    if (diag && tx == (ty >> 2)) {
        int d = (int)(m1w[ty][tx] << (24 - 8 * (ty & 3))) >> 24;
        g_d8[bi + ty] = (signed char)d;
    }
}

// Per-row: full nnz lists (packed 2/uint2), row sums, colEf atomics, scalar-term atomics.
// List entry (row r, col c): idx=c, b=B[r,c], e=E[c,r] (with d_r).
__global__ void __launch_bounds__(256) k_lists() {
    __shared__ unsigned s_ent[CAP];
    __shared__ int scnt;
    __shared__ int wsum[24];
    const int r = blockIdx.x, tid = threadIdx.x, lane = tid & 31, wid = tid >> 5;
    if (tid == 0) scnt = 0;
    __syncthreads();
    const int dr = (int)g_d8[r];

    uint4 bw4 = __ldcs((const uint4*)(g_B8 + (size_t)r * NN) + tid);
    uint4 dw4 = *(const uint4*)(g_d8 + tid * 16);
    unsigned bw[4] = {bw4.x, bw4.y, bw4.z, bw4.w};
    unsigned dw[4] = {dw4.x, dw4.y, dw4.z, dw4.w};

    int sB = 0, sBd = 0, sE = 0, nzc = 0;
    unsigned nzm[4], ew[4];
    #pragma unroll
    for (int q = 0; q < 4; q++) {
        unsigned b = bw[q], d = dw[q];
        sB  = __dp4a((int)b, 0x01010101, sB);
        sBd = __dp4a((int)b, (int)d, sBd);
        unsigned e;
        if (d == 0u) {
            e = (unsigned)__vabsss4((int)b);
        } else {
            e = 0;
            #pragma unroll
            for (int t = 0; t < 4; t++) {
                int bt = (int)(b << (24 - 8 * t)) >> 24;
                int dt = (int)(d << (24 - 8 * t)) >> 24;
                int et = dt ? (abs(bt - dt) - 1) : abs(bt);
                e |= ((unsigned)et & 0xFFu) << (8 * t);
            }
        }
        ew[q] = e;
        sE = __dp4a((int)e, 0x01010101, sE);
        nzm[q] = ~__vcmpeq4(b, 0u);
        nzc += __popc(nzm[q]) >> 3;
    }
    // colEf: rows r in D add E[r,c] (E-support subset of B-support)
    if (dr != 0) {
        #pragma unroll
        for (int q = 0; q < 4; q++) {
            unsigned mk = nzm[q];
            while (mk) {
                int bit = __ffs(mk) - 1;
                int t = bit >> 3;
                mk &= ~(0xFFu << (t * 8));
                int et = (int)(ew[q] << (24 - 8 * t)) >> 24;
                if (et) atomicAdd(&g_colEf[tid * 16 + q * 4 + t], et);
            }
        }
    }
    // extraction into staging (order-free)
    int pos = 0;
    if (nzc) pos = atomicAdd(&scnt, nzc);
    #pragma unroll
    for (int q = 0; q < 4; q++) {
        unsigned mk = nzm[q];
        while (mk) {
            int bit = __ffs(mk) - 1;
            int t = bit >> 3;
            mk &= ~(0xFFu << (t * 8));
            int bt = (int)(bw[q] << (24 - 8 * t)) >> 24;
            int ec = dr ? (abs(bt - dr) - 1) : abs(bt);
            if (pos < CAP)
                s_ent[pos] = (unsigned)(tid * 16 + q * 4 + t)
                           | (((unsigned)bt & 0xFFu) << 16)
                           | (((unsigned)ec & 0xFFu) << 24);
            pos++;
        }
    }
    // row-sum reductions
    #pragma unroll
    for (int o = 16; o > 0; o >>= 1) {
        sB  += __shfl_down_sync(0xFFFFFFFFu, sB, o);
        sBd += __shfl_down_sync(0xFFFFFFFFu, sBd, o);
        sE  += __shfl_down_sync(0xFFFFFFFFu, sE, o);
    }
    if (lane == 0) { wsum[wid] = sB; wsum[8 + wid] = sBd; wsum[16 + wid] = sE; }
    __syncthreads();
    if (tid == 0) {
        int a = 0, c = 0, d = 0;
        #pragma unroll
        for (int w = 0; w < 8; w++) { a += wsum[w]; c += wsum[8 + w]; d += wsum[16 + w]; }
        g_rowsE[r] = d;
        // fold scalar reduction terms (order-free modular int64 atomics)
        atomicAdd(&g_T1, (unsigned long long)((long long)c * (long long)a));
        if (dr != 0) {
            atomicAdd(&g_T2, (unsigned long long)((long long)dr * (long long)a));
            atomicAdd(&g_S, (unsigned long long)(long long)dr);
            atomicAdd(&g_TB, (unsigned long long)(long long)d);
            atomicAdd(&g_nD, 1);
        }
    }
    int cnt = min(scnt, CAP);
    if (tid == 0) g_cnt[r] = cnt;
    int cnt4 = (cnt + 3) & ~3;
    for (int t = cnt + tid; t < cnt4; t += 256) s_ent[t] = 0;
    __syncthreads();
    int ng = cnt4 >> 1;
    for (int g = tid; g < ng; g += 256) {
        unsigned e0 = s_ent[2 * g], e1 = s_ent[2 * g + 1];
        unsigned x = (e0 & 0xFFFFu) | ((e1 & 0xFFFFu) << 16);
        unsigned y = __byte_perm(e0 >> 16, e1 >> 16, 0x5410);
        g_list2[(size_t)r * CAPG + g] = make_uint2(x, y);
    }
}

// Sparse traces: triS = tr(B^3), triE = tr(E^3); folds TA and the final balance
// (last finishing block computes the output — threadfence-reduction pattern).
__global__ void __launch_bounds__(256) k_tri(float* __restrict__ out, int out_size) {
    __shared__ uchar2 s_be[NN];      // (B[j,i], E[j,i]) — 8 KB, computed on the fly
    __shared__ uint2 jl[CAPG];
    __shared__ long long redS[8], redE[8];
    const int j = blockIdx.x, tid = threadIdx.x, lane = tid & 31, wid = tid >> 5;

    {   // build s_be from B row j + d vector (dense, round-10 style)
        uint4 b4 = *(const uint4*)(g_B8 + (size_t)j * NN + tid * 16);
        uint4 d4 = *(const uint4*)(g_d8 + tid * 16);
        unsigned bw[4] = {b4.x, b4.y, b4.z, b4.w};
        unsigned dw[4] = {d4.x, d4.y, d4.z, d4.w};
        unsigned wo[8];
        #pragma unroll
        for (int q = 0; q < 4; q++) {
            unsigned b = bw[q], d = dw[q];
            unsigned e;
            if (d == 0u) {
                e = (unsigned)__vabsss4((int)b);
            } else {
                e = 0;
                #pragma unroll
                for (int t = 0; t < 4; t++) {
                    int bt = (int)(b << (24 - 8 * t)) >> 24;
                    int dt = (int)(d << (24 - 8 * t)) >> 24;
                    int et = dt ? (abs(bt - dt) - 1) : abs(bt);
                    e |= ((unsigned)et & 0xFFu) << (8 * t);
                }
            }
            wo[2 * q]     = __byte_perm(b, e, 0x5140);   // (b0,e0,b1,e1)
            wo[2 * q + 1] = __byte_perm(b, e, 0x7362);   // (b2,e2,b3,e3)
        }
        int4* dst = (int4*)((char*)s_be + tid * 32);
        dst[0] = make_int4((int)wo[0], (int)wo[1], (int)wo[2], (int)wo[3]);
        dst[1] = make_int4((int)wo[4], (int)wo[5], (int)wo[6], (int)wo[7]);
    }
    const int cj = g_cnt[j];
    const int njg = ((cj + 3) & ~3) >> 1;
    for (int t = tid; t < njg; t += 256) jl[t] = g_list2[(size_t)j * CAPG + t];
    __syncthreads();

    int aS = 0, aE = 0;
    for (int kk = wid; kk < cj; kk += 8) {
        uint2 w = jl[kk >> 1];
        int hi = kk & 1;
        int k = hi ? (int)(w.x >> 16) : (int)(w.x & 0xFFFFu);
        int bkj = hi ? ((int)(w.y << 8) >> 24) : ((int)(w.y << 24) >> 24);
        int ekj = hi ? ((int)w.y >> 24)        : ((int)(w.y << 16) >> 24);
        const uint4* lk = (const uint4*)(g_list2 + (size_t)k * CAPG);
        int ck4 = (__ldg(&g_cnt[k]) + 3) >> 2;
        int sk = 0, ek = 0;
        for (int t = lane; t < ck4; t += 32) {
            uint4 w4 = __ldg(&lk[t]);
            {
                int i0 = (int)(w4.x & 0xFFFFu), i1 = (int)(w4.x >> 16);
                unsigned v0 = *(const unsigned short*)&s_be[i0];
                unsigned v1 = *(const unsigned short*)&s_be[i1];
                unsigned be2 = __byte_perm(v0, v1, 0x5410);
                sk = __dp4a((int)(w4.y & 0x00FF00FFu), (int)be2, sk);
                ek = __dp4a((int)(w4.y & 0xFF00FF00u), (int)be2, ek);
            }
            {
                int i0 = (int)(w4.z & 0xFFFFu), i1 = (int)(w4.z >> 16);
                unsigned v0 = *(const unsigned short*)&s_be[i0];
                unsigned v1 = *(const unsigned short*)&s_be[i1];
                unsigned be2 = __byte_perm(v0, v1, 0x5410);
                sk = __dp4a((int)(w4.w & 0x00FF00FFu), (int)be2, sk);
                ek = __dp4a((int)(w4.w & 0xFF00FF00u), (int)be2, ek);
            }
        }
        aS += bkj * sk;
        aE += ekj * ek;
    }
    #pragma unroll
    for (int o = 16; o > 0; o >>= 1) {
        aS += __shfl_down_sync(0xFFFFFFFFu, aS, o);
        aE += __shfl_down_sync(0xFFFFFFFFu, aE, o);
    }
    if (lane == 0) { redS[wid] = aS; redE[wid] = aE; }
    __syncthreads();
    if (tid == 0) {
        long long s = 0, t = 0;
        #pragma unroll
        for (int w = 0; w < 8; w++) { s += redS[w]; t += redE[w]; }
        atomicAdd(&g_triS, (unsigned long long)s);
        atomicAdd(&g_triE, (unsigned long long)t);
        atomicAdd(&g_TA, (unsigned long long)((long long)g_colEf[j] * (long long)g_rowsE[j]));
        __threadfence();
        unsigned prev = atomicAdd(&g_done, 1u);
        if (prev == (unsigned)(NN - 1)) {
            // all blocks' atomics globally visible (each fenced before g_done bump)
            long long triS = (long long)atomicAdd(&g_triS, 0ull);
            long long triE = (long long)atomicAdd(&g_triE, 0ull);
            long long T1 = (long long)atomicAdd(&g_T1, 0ull);
            long long T2 = (long long)atomicAdd(&g_T2, 0ull);
            long long Sv = (long long)atomicAdd(&g_S, 0ull);
            long long TA = (long long)atomicAdd(&g_TA, 0ull);
            long long TB = (long long)atomicAdd(&g_TB, 0ull);
            long long nD = (long long)atomicAdd(&g_nD, 0);
            // tr(A^3)  = tr(B^3) - 3*T1 + 3*S*T2 - S^3
            // tr(|A|^3)= tr(E^3) + 3*TA + 3*|D|*TB + |D|^3
            long long tr3  = triS - 3 * T1 + 3 * Sv * T2 - Sv * Sv * Sv;
            long long tr3a = triE + 3 * TA + 3 * nD * TB + nD * nD * nD;
            out[out_size - 1] = (float)(0.5 * (1.0 + (double)tr3 / (double)tr3a));
        }
    }
}

// ---------------- launch ----------------
extern "C" void kernel_launch(void* const* d_in, const int* in_sizes, int n_in,
                              void* d_out, int out_size) {
    const float* ori = (const float*)d_in[0];
    const float* cp  = (const float*)d_in[1];
    const float* u   = (const float*)d_in[2];
    float* out = (float*)d_out;

    k_fuse<<<dim3(128, 128), dim3(8, 32)>>>(ori, cp, u, out);
    k_lists<<<NN, 256>>>();
    k_tri<<<NN, 256>>>(out, out_size);
}

// round 14
// speedup vs baseline: 1.1124x; 1.0164x over previous
#include <cuda_runtime.h>
#include <math.h>
#include <stdint.h>

#define NN 4096
#define CAP 256
#define CAPG (CAP / 2)

// ---------------- device globals (allocation-free scratch) ----------------
__device__ __align__(16) signed char g_B8[(size_t)NN * NN];   // B = m + m^T
__device__ __align__(16) signed char g_d8[NN];
__device__ int g_nD;
__device__ __align__(16) uint2 g_list2[(size_t)NN * CAPG];    // 2 entries per uint2
__device__ int g_cnt[NN];
__device__ __align__(16) unsigned short g_cnt16[NN];
__device__ int g_rowsE[NN], g_colEf[NN];
__device__ unsigned long long g_triS, g_triE;
__device__ unsigned long long g_T1, g_T2, g_S, g_TA, g_TB;
__device__ unsigned g_done;

// Fused: mod_adj + B = m + m^T + diag + zeroing of accumulators.
// hard = 1 <=> logit(p)+logit(u) > 0 <=> p + (u-1) > 0 (u-1 exact by Sterbenz).
__global__ void k_fuse(const float* __restrict__ ori, const float* __restrict__ cp,
                       const float* __restrict__ u, float* __restrict__ mod) {
    __shared__ unsigned m1w[32][9];
    __shared__ unsigned m2w[32][9];
    const int bx = blockIdx.x, by = blockIdx.y;
    if (bx < by) return;
    const int bi = by * 32, bj = bx * 32;
    const int tx = threadIdx.x;   // 0..7
    const int ty = threadIdx.y;   // 0..31
    const int tid = ty * 8 + tx;
    const bool diag = (bx == by);

    if (diag && tid < 32) g_colEf[bi + tid] = 0;
    if (bx == 0 && by == 0 && tid == 0) {
        g_triS = 0ull; g_triE = 0ull; g_nD = 0; g_done = 0u;
        g_T1 = 0ull; g_T2 = 0ull; g_S = 0ull; g_TA = 0ull; g_TB = 0ull;
    }

    {
        size_t idx = ((size_t)(bi + ty) * NN + bj + tx * 4) >> 2;
        float4 o = __ldcs((const float4*)ori + idx);
        float4 c = __ldcs((const float4*)cp + idx);
        float4 w = __ldcs((const float4*)u + idx);
        float4 m;
        m.x = (c.x + (w.x - 1.0f) > 0.0f) ? -o.x : o.x;
        m.y = (c.y + (w.y - 1.0f) > 0.0f) ? -o.y : o.y;
        m.z = (c.z + (w.z - 1.0f) > 0.0f) ? -o.z : o.z;
        m.w = (c.w + (w.w - 1.0f) > 0.0f) ? -o.w : o.w;
        __stcs((float4*)mod + idx, m);
        m1w[ty][tx] = ((unsigned)(int)m.x & 0xFFu)
                    | (((unsigned)(int)m.y & 0xFFu) << 8)
                    | (((unsigned)(int)m.z & 0xFFu) << 16)
                    | (((unsigned)(int)m.w & 0xFFu) << 24);
    }
    if (!diag) {
        size_t idx = ((size_t)(bj + ty) * NN + bi + tx * 4) >> 2;
        float4 o = __ldcs((const float4*)ori + idx);
        float4 c = __ldcs((const float4*)cp + idx);
        float4 w = __ldcs((const float4*)u + idx);
        float4 m;
        m.x = (c.x + (w.x - 1.0f) > 0.0f) ? -o.x : o.x;
        m.y = (c.y + (w.y - 1.0f) > 0.0f) ? -o.y : o.y;
        m.z = (c.z + (w.z - 1.0f) > 0.0f) ? -o.z : o.z;
        m.w = (c.w + (w.w - 1.0f) > 0.0f) ? -o.w : o.w;
        __stcs((float4*)mod + idx, m);
        m2w[ty][tx] = ((unsigned)(int)m.x & 0xFFu)
                    | (((unsigned)(int)m.y & 0xFFu) << 8)
                    | (((unsigned)(int)m.z & 0xFFu) << 16)
                    | (((unsigned)(int)m.w & 0xFFu) << 24);
    }
    __syncthreads();
    {   // B tile1: rows bi+ty, cols bj+tx*4..+3
        unsigned w1 = m1w[ty][tx];
        unsigned out = 0;
        #pragma unroll
        for (int q = 0; q < 4; q++) {
            int a = (int)(w1 << (24 - 8 * q)) >> 24;
            unsigned wt = diag ? m1w[tx * 4 + q][ty >> 2] : m2w[tx * 4 + q][ty >> 2];
            int b = (int)(wt << (24 - 8 * (ty & 3))) >> 24;
            out |= ((unsigned)(a + b) & 0xFFu) << (8 * q);
        }
        *(unsigned*)(g_B8 + (size_t)(bi + ty) * NN + bj + tx * 4) = out;
    }
    if (!diag) {  // B tile2: rows bj+ty, cols bi+tx*4..+3
        unsigned w1 = m2w[ty][tx];
        unsigned out = 0;
        #pragma unroll
        for (int q = 0; q < 4; q++) {
            int a = (int)(w1 << (24 - 8 * q)) >> 24;
            unsigned wt = m1w[tx * 4 + q][ty >> 2];
            int b = (int)(wt << (24 - 8 * (ty & 3))) >> 24;
            out |= ((unsigned)(a + b) & 0xFFu) << (8 * q);
        }
        *(unsigned*)(g_B8 + (size_t)(bj + ty) * NN + bi + tx * 4) = out;
    }
    if (diag && tx == (ty >> 2)) {
        int d = (int)(m1w[ty][tx] << (24 - 8 * (ty & 3))) >> 24;
        g_d8[bi + ty] = (signed char)d;
    }
}

// Per-row: full nnz lists (packed 2/uint2), row sums, colEf atomics, scalar-term atomics.
// List entry (row r, col c): idx=c, b=B[r,c], e=E[c,r] (with d_r).
__global__ void __launch_bounds__(256) k_lists() {
    __shared__ unsigned s_ent[CAP];
    __shared__ int scnt;
    __shared__ int wsum[24];
    const int r = blockIdx.x, tid = threadIdx.x, lane = tid & 31, wid = tid >> 5;
    if (tid == 0) scnt = 0;
    __syncthreads();
    const int dr = (int)g_d8[r];

    uint4 bw4 = __ldcs((const uint4*)(g_B8 + (size_t)r * NN) + tid);
    uint4 dw4 = *(const uint4*)(g_d8 + tid * 16);
    unsigned bw[4] = {bw4.x, bw4.y, bw4.z, bw4.w};
    unsigned dw[4] = {dw4.x, dw4.y, dw4.z, dw4.w};

    int sB = 0, sBd = 0, sE = 0, nzc = 0;
    unsigned nzm[4], ew[4];
    #pragma unroll
    for (int q = 0; q < 4; q++) {
        unsigned b = bw[q], d = dw[q];
        sB  = __dp4a((int)b, 0x01010101, sB);
        sBd = __dp4a((int)b, (int)d, sBd);
        unsigned e;
        if (d == 0u) {
            e = (unsigned)__vabsss4((int)b);
        } else {
            e = 0;
            #pragma unroll
            for (int t = 0; t < 4; t++) {
                int bt = (int)(b << (24 - 8 * t)) >> 24;
                int dt = (int)(d << (24 - 8 * t)) >> 24;
                int et = dt ? (abs(bt - dt) - 1) : abs(bt);
                e |= ((unsigned)et & 0xFFu) << (8 * t);
            }
        }
        ew[q] = e;
        sE = __dp4a((int)e, 0x01010101, sE);
        nzm[q] = ~__vcmpeq4(b, 0u);
        nzc += __popc(nzm[q]) >> 3;
    }
    // colEf: rows r in D add E[r,c] (E-support subset of B-support)
    if (dr != 0) {
        #pragma unroll
        for (int q = 0; q < 4; q++) {
            unsigned mk = nzm[q];
            while (mk) {
                int bit = __ffs(mk) - 1;
                int t = bit >> 3;
                mk &= ~(0xFFu << (t * 8));
                int et = (int)(ew[q] << (24 - 8 * t)) >> 24;
                if (et) atomicAdd(&g_colEf[tid * 16 + q * 4 + t], et);
            }
        }
    }
    // extraction into staging (order-free)
    int pos = 0;
    if (nzc) pos = atomicAdd(&scnt, nzc);
    #pragma unroll
    for (int q = 0; q < 4; q++) {
        unsigned mk = nzm[q];
        while (mk) {
            int bit = __ffs(mk) - 1;
            int t = bit >> 3;
            mk &= ~(0xFFu << (t * 8));
            int bt = (int)(bw[q] << (24 - 8 * t)) >> 24;
            int ec = dr ? (abs(bt - dr) - 1) : abs(bt);
            if (pos < CAP)
                s_ent[pos] = (unsigned)(tid * 16 + q * 4 + t)
                           | (((unsigned)bt & 0xFFu) << 16)
                           | (((unsigned)ec & 0xFFu) << 24);
            pos++;
        }
    }
    // row-sum reductions
    #pragma unroll
    for (int o = 16; o > 0; o >>= 1) {
        sB  += __shfl_down_sync(0xFFFFFFFFu, sB, o);
        sBd += __shfl_down_sync(0xFFFFFFFFu, sBd, o);
        sE  += __shfl_down_sync(0xFFFFFFFFu, sE, o);
    }
    if (lane == 0) { wsum[wid] = sB; wsum[8 + wid] = sBd; wsum[16 + wid] = sE; }
    __syncthreads();
    if (tid == 0) {
        int a = 0, c = 0, d = 0;
        #pragma unroll
        for (int w = 0; w < 8; w++) { a += wsum[w]; c += wsum[8 + w]; d += wsum[16 + w]; }
        g_rowsE[r] = d;
        // fold scalar reduction terms (order-free modular int64 atomics)
        atomicAdd(&g_T1, (unsigned long long)((long long)c * (long long)a));
        if (dr != 0) {
            atomicAdd(&g_T2, (unsigned long long)((long long)dr * (long long)a));
            atomicAdd(&g_S, (unsigned long long)(long long)dr);
            atomicAdd(&g_TB, (unsigned long long)(long long)d);
            atomicAdd(&g_nD, 1);
        }
    }
    int cnt = min(scnt, CAP);
    if (tid == 0) { g_cnt[r] = cnt; g_cnt16[r] = (unsigned short)cnt; }
    int cnt4 = (cnt + 3) & ~3;
    for (int t = cnt + tid; t < cnt4; t += 256) s_ent[t] = 0;
    __syncthreads();
    int ng = cnt4 >> 1;
    for (int g = tid; g < ng; g += 256) {
        unsigned e0 = s_ent[2 * g], e1 = s_ent[2 * g + 1];
        unsigned x = (e0 & 0xFFFFu) | ((e1 & 0xFFFFu) << 16);
        unsigned y = __byte_perm(e0 >> 16, e1 >> 16, 0x5410);
        g_list2[(size_t)r * CAPG + g] = make_uint2(x, y);
    }
}

// Sparse traces: triS = tr(B^3), triE = tr(E^3); folds TA and the final balance
// (last finishing block computes the output — threadfence-reduction pattern).
__global__ void __launch_bounds__(256) k_tri(float* __restrict__ out, int out_size) {
    __shared__ uchar2 s_be[NN];               // 8 KB: (B[j,i], E[j,i]) bytes
    __shared__ unsigned short s_cnt[NN];      // 8 KB: all row counts
    __shared__ uint2 jl[CAPG];
    __shared__ long long redS[8], redE[8];
    const int j = blockIdx.x, tid = threadIdx.x, lane = tid & 31, wid = tid >> 5;

    // stage all counts (8 KB, coalesced)
    ((uint4*)s_cnt)[tid] = ((const uint4*)g_cnt16)[tid];
    ((uint4*)s_cnt)[tid + 256] = ((const uint4*)g_cnt16)[tid + 256];

    {   // build s_be from B row j + d vector (dense)
        uint4 b4 = *(const uint4*)(g_B8 + (size_t)j * NN + tid * 16);
        uint4 d4 = *(const uint4*)(g_d8 + tid * 16);
        unsigned bw[4] = {b4.x, b4.y, b4.z, b4.w};
        unsigned dw[4] = {d4.x, d4.y, d4.z, d4.w};
        unsigned wo[8];
        #pragma unroll
        for (int q = 0; q < 4; q++) {
            unsigned b = bw[q], d = dw[q];
            unsigned e;
            if (d == 0u) {
                e = (unsigned)__vabsss4((int)b);
            } else {
                e = 0;
                #pragma unroll
                for (int t = 0; t < 4; t++) {
                    int bt = (int)(b << (24 - 8 * t)) >> 24;
                    int dt = (int)(d << (24 - 8 * t)) >> 24;
                    int et = dt ? (abs(bt - dt) - 1) : abs(bt);
                    e |= ((unsigned)et & 0xFFu) << (8 * t);
                }
            }
            wo[2 * q]     = __byte_perm(b, e, 0x5140);   // (b0,e0,b1,e1)
            wo[2 * q + 1] = __byte_perm(b, e, 0x7362);   // (b2,e2,b3,e3)
        }
        int4* dst = (int4*)((char*)s_be + tid * 32);
        dst[0] = make_int4((int)wo[0], (int)wo[1], (int)wo[2], (int)wo[3]);
        dst[1] = make_int4((int)wo[4], (int)wo[5], (int)wo[6], (int)wo[7]);
    }
    const int cj = g_cnt[j];
    const int njg = ((cj + 3) & ~3) >> 1;
    for (int t = tid; t < njg; t += 256) jl[t] = g_list2[(size_t)j * CAPG + t];
    __syncthreads();

    int aS = 0, aE = 0;
    for (int kk = wid; kk < cj; kk += 8) {
        uint2 w = jl[kk >> 1];
        int hi = kk & 1;
        int k = hi ? (int)(w.x >> 16) : (int)(w.x & 0xFFFFu);
        int bkj = hi ? ((int)(w.y << 8) >> 24) : ((int)(w.y << 24) >> 24);
        int ekj = hi ? ((int)w.y >> 24)        : ((int)(w.y << 16) >> 24);
        const uint4* lk = (const uint4*)(g_list2 + (size_t)k * CAPG);
        int ck4 = ((int)s_cnt[k] + 3) >> 2;
        int sk = 0, ek = 0;
        for (int t = lane; t < ck4; t += 32) {
            uint4 w4 = __ldg(&lk[t]);
            {
                int i0 = (int)(w4.x & 0xFFFFu), i1 = (int)(w4.x >> 16);
                unsigned v0 = *(const unsigned short*)&s_be[i0];
                unsigned v1 = *(const unsigned short*)&s_be[i1];
                unsigned be2 = __byte_perm(v0, v1, 0x5410);
                sk = __dp4a((int)(w4.y & 0x00FF00FFu), (int)be2, sk);
                ek = __dp4a((int)(w4.y & 0xFF00FF00u), (int)be2, ek);
            }
            {
                int i0 = (int)(w4.z & 0xFFFFu), i1 = (int)(w4.z >> 16);
                unsigned v0 = *(const unsigned short*)&s_be[i0];
                unsigned v1 = *(const unsigned short*)&s_be[i1];
                unsigned be2 = __byte_perm(v0, v1, 0x5410);
                sk = __dp4a((int)(w4.w & 0x00FF00FFu), (int)be2, sk);
                ek = __dp4a((int)(w4.w & 0xFF00FF00u), (int)be2, ek);
            }
        }
        aS += bkj * sk;
        aE += ekj * ek;
    }
    #pragma unroll
    for (int o = 16; o > 0; o >>= 1) {
        aS += __shfl_down_sync(0xFFFFFFFFu, aS, o);
        aE += __shfl_down_sync(0xFFFFFFFFu, aE, o);
    }
    if (lane == 0) { redS[wid] = aS; redE[wid] = aE; }
    __syncthreads();
    if (tid == 0) {
        long long s = 0, t = 0;
        #pragma unroll
        for (int w = 0; w < 8; w++) { s += redS[w]; t += redE[w]; }
        atomicAdd(&g_triS, (unsigned long long)s);
        atomicAdd(&g_triE, (unsigned long long)t);
        atomicAdd(&g_TA, (unsigned long long)((long long)g_colEf[j] * (long long)g_rowsE[j]));
        __threadfence();
        unsigned prev = atomicAdd(&g_done, 1u);
        if (prev == (unsigned)(NN - 1)) {
            // all blocks' atomics globally visible (each fenced before g_done bump)
            long long triS = (long long)atomicAdd(&g_triS, 0ull);
            long long triE = (long long)atomicAdd(&g_triE, 0ull);
            long long T1 = (long long)atomicAdd(&g_T1, 0ull);
            long long T2 = (long long)atomicAdd(&g_T2, 0ull);
            long long Sv = (long long)atomicAdd(&g_S, 0ull);
            long long TA = (long long)atomicAdd(&g_TA, 0ull);
            long long TB = (long long)atomicAdd(&g_TB, 0ull);
            long long nD = (long long)atomicAdd(&g_nD, 0);
            // tr(A^3)  = tr(B^3) - 3*T1 + 3*S*T2 - S^3
            // tr(|A|^3)= tr(E^3) + 3*TA + 3*|D|*TB + |D|^3
            long long tr3  = triS - 3 * T1 + 3 * Sv * T2 - Sv * Sv * Sv;
            long long tr3a = triE + 3 * TA + 3 * nD * TB + nD * nD * nD;
            out[out_size - 1] = (float)(0.5 * (1.0 + (double)tr3 / (double)tr3a));
        }
    }
}

// ---------------- launch ----------------
extern "C" void kernel_launch(void* const* d_in, const int* in_sizes, int n_in,
                              void* d_out, int out_size) {
    const float* ori = (const float*)d_in[0];
    const float* cp  = (const float*)d_in[1];
    const float* u   = (const float*)d_in[2];
    float* out = (float*)d_out;

    k_fuse<<<dim3(128, 128), dim3(8, 32)>>>(ori, cp, u, out);
    k_lists<<<NN, 256>>>();
    k_tri<<<NN, 256>>>(out, out_size);
}

// round 15
// speedup vs baseline: 1.1223x; 1.0089x over previous
#include <cuda_runtime.h>
#include <math.h>
#include <stdint.h>

#define NN 4096
#define CAP 256
#define CAPG (CAP / 2)
#define NTRI 8256   // 128*129/2 triangular blocks

// ---------------- device globals (allocation-free scratch) ----------------
__device__ __align__(16) signed char g_B8[(size_t)NN * NN];   // B = m + m^T
__device__ __align__(16) signed char g_d8[NN];
__device__ int g_nD;
__device__ __align__(16) uint2 g_list2[(size_t)NN * CAPG];    // 2 entries per uint2
__device__ int g_cnt[NN];
__device__ __align__(16) unsigned short g_cnt16[NN];
__device__ int g_rowsE[NN], g_colEf[NN];
__device__ unsigned long long g_triS, g_triE;
__device__ unsigned long long g_T1, g_T2, g_S, g_TA, g_TB;
__device__ unsigned g_done;

static __device__ __forceinline__ void gdc_wait() {
    asm volatile("griddepcontrol.wait;" ::: "memory");
}
static __device__ __forceinline__ void gdc_launch() {
    asm volatile("griddepcontrol.launch_dependents;" ::: "memory");
}

// Fused: mod_adj + B = m + m^T + diag + zeroing of accumulators.
// hard = 1 <=> logit(p)+logit(u) > 0 <=> p + (u-1) > 0 (u-1 exact by Sterbenz).
// Triangular grid: linear block -> (bx >= by).
__global__ void k_fuse(const float* __restrict__ ori, const float* __restrict__ cp,
                       const float* __restrict__ u, float* __restrict__ mod) {
    __shared__ unsigned m1w[32][9];
    __shared__ unsigned m2w[32][9];
    const int t = blockIdx.x;
    int by = ((int)(257.0f - __fsqrt_rn(66049.0f - 8.0f * (float)t))) >> 1;
    while (by * 128 - ((by * (by - 1)) >> 1) > t) by--;
    while ((by + 1) * 128 - (((by + 1) * by) >> 1) <= t) by++;
    const int bx = by + (t - (by * 128 - ((by * (by - 1)) >> 1)));
    const int bi = by * 32, bj = bx * 32;
    const int tx = threadIdx.x;   // 0..7
    const int ty = threadIdx.y;   // 0..31
    const int tid = ty * 8 + tx;
    const bool diag = (bx == by);

    if (diag && tid < 32) g_colEf[bi + tid] = 0;
    if (t == 0 && tid == 0) {
        g_triS = 0ull; g_triE = 0ull; g_nD = 0; g_done = 0u;
        g_T1 = 0ull; g_T2 = 0ull; g_S = 0ull; g_TA = 0ull; g_TB = 0ull;
    }

    {
        size_t idx = ((size_t)(bi + ty) * NN + bj + tx * 4) >> 2;
        float4 o = __ldcs((const float4*)ori + idx);
        float4 c = __ldcs((const float4*)cp + idx);
        float4 w = __ldcs((const float4*)u + idx);
        float4 m;
        m.x = (c.x + (w.x - 1.0f) > 0.0f) ? -o.x : o.x;
        m.y = (c.y + (w.y - 1.0f) > 0.0f) ? -o.y : o.y;
        m.z = (c.z + (w.z - 1.0f) > 0.0f) ? -o.z : o.z;
        m.w = (c.w + (w.w - 1.0f) > 0.0f) ? -o.w : o.w;
        __stcs((float4*)mod + idx, m);
        m1w[ty][tx] = ((unsigned)(int)m.x & 0xFFu)
                    | (((unsigned)(int)m.y & 0xFFu) << 8)
                    | (((unsigned)(int)m.z & 0xFFu) << 16)
                    | (((unsigned)(int)m.w & 0xFFu) << 24);
    }
    if (!diag) {
        size_t idx = ((size_t)(bj + ty) * NN + bi + tx * 4) >> 2;
        float4 o = __ldcs((const float4*)ori + idx);
        float4 c = __ldcs((const float4*)cp + idx);
        float4 w = __ldcs((const float4*)u + idx);
        float4 m;
        m.x = (c.x + (w.x - 1.0f) > 0.0f) ? -o.x : o.x;
        m.y = (c.y + (w.y - 1.0f) > 0.0f) ? -o.y : o.y;
        m.z = (c.z + (w.z - 1.0f) > 0.0f) ? -o.z : o.z;
        m.w = (c.w + (w.w - 1.0f) > 0.0f) ? -o.w : o.w;
        __stcs((float4*)mod + idx, m);
        m2w[ty][tx] = ((unsigned)(int)m.x & 0xFFu)
                    | (((unsigned)(int)m.y & 0xFFu) << 8)
                    | (((unsigned)(int)m.z & 0xFFu) << 16)
                    | (((unsigned)(int)m.w & 0xFFu) << 24);
    }
    __syncthreads();
    {   // B tile1: rows bi+ty, cols bj+tx*4..+3
        unsigned w1 = m1w[ty][tx];
        unsigned out = 0;
        #pragma unroll
        for (int q = 0; q < 4; q++) {
            int a = (int)(w1 << (24 - 8 * q)) >> 24;
            unsigned wt = diag ? m1w[tx * 4 + q][ty >> 2] : m2w[tx * 4 + q][ty >> 2];
            int b = (int)(wt << (24 - 8 * (ty & 3))) >> 24;
            out |= ((unsigned)(a + b) & 0xFFu) << (8 * q);
        }
        *(unsigned*)(g_B8 + (size_t)(bi + ty) * NN + bj + tx * 4) = out;
    }
    if (!diag) {  // B tile2: rows bj+ty, cols bi+tx*4..+3
        unsigned w1 = m2w[ty][tx];
        unsigned out = 0;
        #pragma unroll
        for (int q = 0; q < 4; q++) {
            int a = (int)(w1 << (24 - 8 * q)) >> 24;
            unsigned wt = m1w[tx * 4 + q][ty >> 2];
            int b = (int)(wt << (24 - 8 * (ty & 3))) >> 24;
            out |= ((unsigned)(a + b) & 0xFFu) << (8 * q);
        }
        *(unsigned*)(g_B8 + (size_t)(bj + ty) * NN + bi + tx * 4) = out;
    }
    if (diag && tx == (ty >> 2)) {
        int d = (int)(m1w[ty][tx] << (24 - 8 * (ty & 3))) >> 24;
        g_d8[bi + ty] = (signed char)d;
    }
    gdc_launch();
}

// Per-row: full nnz lists (packed 2/uint2), row sums, colEf atomics, scalar-term atomics.
// List entry (row r, col c): idx=c, b=B[r,c], e=E[c,r] (with d_r).
__global__ void __launch_bounds__(256) k_lists() {
    __shared__ unsigned s_ent[CAP];
    __shared__ int scnt;
    __shared__ int wsum[24];
    const int r = blockIdx.x, tid = threadIdx.x, lane = tid & 31, wid = tid >> 5;
    if (tid == 0) scnt = 0;
    gdc_wait();    // PDL: wait for k_fuse's B/d before reading
    __syncthreads();
    const int dr = (int)g_d8[r];

    uint4 bw4 = __ldcs((const uint4*)(g_B8 + (size_t)r * NN) + tid);
    uint4 dw4 = *(const uint4*)(g_d8 + tid * 16);
    unsigned bw[4] = {bw4.x, bw4.y, bw4.z, bw4.w};
    unsigned dw[4] = {dw4.x, dw4.y, dw4.z, dw4.w};

    int sB = 0, sBd = 0, sE = 0, nzc = 0;
    unsigned nzm[4], ew[4];
    #pragma unroll
    for (int q = 0; q < 4; q++) {
        unsigned b = bw[q], d = dw[q];
        sB  = __dp4a((int)b, 0x01010101, sB);
        sBd = __dp4a((int)b, (int)d, sBd);
        unsigned e;
        if (d == 0u) {
            e = (unsigned)__vabsss4((int)b);
        } else {
            e = 0;
            #pragma unroll
            for (int t = 0; t < 4; t++) {
                int bt = (int)(b << (24 - 8 * t)) >> 24;
                int dt = (int)(d << (24 - 8 * t)) >> 24;
                int et = dt ? (abs(bt - dt) - 1) : abs(bt);
                e |= ((unsigned)et & 0xFFu) << (8 * t);
            }
        }
        ew[q] = e;
        sE = __dp4a((int)e, 0x01010101, sE);
        nzm[q] = ~__vcmpeq4(b, 0u);
        nzc += __popc(nzm[q]) >> 3;
    }
    // colEf: rows r in D add E[r,c] (E-support subset of B-support)
    if (dr != 0) {
        #pragma unroll
        for (int q = 0; q < 4; q++) {
            unsigned mk = nzm[q];
            while (mk) {
                int bit = __ffs(mk) - 1;
                int t = bit >> 3;
                mk &= ~(0xFFu << (t * 8));
                int et = (int)(ew[q] << (24 - 8 * t)) >> 24;
                if (et) atomicAdd(&g_colEf[tid * 16 + q * 4 + t], et);
            }
        }
    }
    // extraction into staging (order-free)
    int pos = 0;
    if (nzc) pos = atomicAdd(&scnt, nzc);
    #pragma unroll
    for (int q = 0; q < 4; q++) {
        unsigned mk = nzm[q];
        while (mk) {
            int bit = __ffs(mk) - 1;
            int t = bit >> 3;
            mk &= ~(0xFFu << (t * 8));
            int bt = (int)(bw[q] << (24 - 8 * t)) >> 24;
            int ec = dr ? (abs(bt - dr) - 1) : abs(bt);
            if (pos < CAP)
                s_ent[pos] = (unsigned)(tid * 16 + q * 4 + t)
                           | (((unsigned)bt & 0xFFu) << 16)
                           | (((unsigned)ec & 0xFFu) << 24);
            pos++;
        }
    }
    // row-sum reductions
    #pragma unroll
    for (int o = 16; o > 0; o >>= 1) {
        sB  += __shfl_down_sync(0xFFFFFFFFu, sB, o);
        sBd += __shfl_down_sync(0xFFFFFFFFu, sBd, o);
        sE  += __shfl_down_sync(0xFFFFFFFFu, sE, o);
    }
    if (lane == 0) { wsum[wid] = sB; wsum[8 + wid] = sBd; wsum[16 + wid] = sE; }
    __syncthreads();
    if (tid == 0) {
        int a = 0, c = 0, d = 0;
        #pragma unroll
        for (int w = 0; w < 8; w++) { a += wsum[w]; c += wsum[8 + w]; d += wsum[16 + w]; }
        g_rowsE[r] = d;
        atomicAdd(&g_T1, (unsigned long long)((long long)c * (long long)a));
        if (dr != 0) {
            atomicAdd(&g_T2, (unsigned long long)((long long)dr * (long long)a));
            atomicAdd(&g_S, (unsigned long long)(long long)dr);
            atomicAdd(&g_TB, (unsigned long long)(long long)d);
            atomicAdd(&g_nD, 1);
        }
    }
    int cnt = min(scnt, CAP);
    if (tid == 0) { g_cnt[r] = cnt; g_cnt16[r] = (unsigned short)cnt; }
    int cnt4 = (cnt + 3) & ~3;
    for (int t = cnt + tid; t < cnt4; t += 256) s_ent[t] = 0;
    __syncthreads();
    int ng = cnt4 >> 1;
    for (int g = tid; g < ng; g += 256) {
        unsigned e0 = s_ent[2 * g], e1 = s_ent[2 * g + 1];
        unsigned x = (e0 & 0xFFFFu) | ((e1 & 0xFFFFu) << 16);
        unsigned y = __byte_perm(e0 >> 16, e1 >> 16, 0x5410);
        g_list2[(size_t)r * CAPG + g] = make_uint2(x, y);
    }
    gdc_launch();
}

// Sparse traces: triS = tr(B^3), triE = tr(E^3); folds TA and the final balance
// (last finishing block computes the output — threadfence-reduction pattern).
__global__ void __launch_bounds__(256) k_tri(float* __restrict__ out, int out_size) {
    __shared__ uchar2 s_be[NN];               // 8 KB: (B[j,i], E[j,i]) bytes
    __shared__ unsigned short s_cnt[NN];      // 8 KB: all row counts
    __shared__ uint2 jl[CAPG];
    __shared__ long long redS[8], redE[8];
    const int j = blockIdx.x, tid = threadIdx.x, lane = tid & 31, wid = tid >> 5;

    {   // build s_be from B row j + d vector — depends ONLY on k_fuse, so it
        // runs BEFORE the PDL wait and overlaps k_lists' drain.
        uint4 b4 = *(const uint4*)(g_B8 + (size_t)j * NN + tid * 16);
        uint4 d4 = *(const uint4*)(g_d8 + tid * 16);
        unsigned bw[4] = {b4.x, b4.y, b4.z, b4.w};
        unsigned dw[4] = {d4.x, d4.y, d4.z, d4.w};
        unsigned wo[8];
        #pragma unroll
        for (int q = 0; q < 4; q++) {
            unsigned b = bw[q], d = dw[q];
            unsigned e;
            if (d == 0u) {
                e = (unsigned)__vabsss4((int)b);
            } else {
                e = 0;
                #pragma unroll
                for (int t = 0; t < 4; t++) {
                    int bt = (int)(b << (24 - 8 * t)) >> 24;
                    int dt = (int)(d << (24 - 8 * t)) >> 24;
                    int et = dt ? (abs(bt - dt) - 1) : abs(bt);
                    e |= ((unsigned)et & 0xFFu) << (8 * t);
                }
            }
            wo[2 * q]     = __byte_perm(b, e, 0x5140);   // (b0,e0,b1,e1)
            wo[2 * q + 1] = __byte_perm(b, e, 0x7362);   // (b2,e2,b3,e3)
        }
        int4* dst = (int4*)((char*)s_be + tid * 32);
        dst[0] = make_int4((int)wo[0], (int)wo[1], (int)wo[2], (int)wo[3]);
        dst[1] = make_int4((int)wo[4], (int)wo[5], (int)wo[6], (int)wo[7]);
    }

    gdc_wait();    // PDL: wait for k_lists' lists/counts before reading them

    // stage all counts (8 KB, coalesced)
    ((uint4*)s_cnt)[tid] = ((const uint4*)g_cnt16)[tid];
    ((uint4*)s_cnt)[tid + 256] = ((const uint4*)g_cnt16)[tid + 256];
    const int cj = g_cnt[j];
    const int njg = ((cj + 3) & ~3) >> 1;
    for (int t = tid; t < njg; t += 256) jl[t] = g_list2[(size_t)j * CAPG + t];
    __syncthreads();

    int aS = 0, aE = 0;
    for (int kk = wid; kk < cj; kk += 8) {
        uint2 w = jl[kk >> 1];
        int hi = kk & 1;
        int k = hi ? (int)(w.x >> 16) : (int)(w.x & 0xFFFFu);
        int bkj = hi ? ((int)(w.y << 8) >> 24) : ((int)(w.y << 24) >> 24);
        int ekj = hi ? ((int)w.y >> 24)        : ((int)(w.y << 16) >> 24);
        const uint4* lk = (const uint4*)(g_list2 + (size_t)k * CAPG);
        int ck4 = ((int)s_cnt[k] + 3) >> 2;
        int sk = 0, ek = 0;
        for (int t = lane; t < ck4; t += 32) {
            uint4 w4 = __ldg(&lk[t]);
            {
                int i0 = (int)(w4.x & 0xFFFFu), i1 = (int)(w4.x >> 16);
                unsigned v0 = *(const unsigned short*)&s_be[i0];
                unsigned v1 = *(const unsigned short*)&s_be[i1];
                unsigned be2 = __byte_perm(v0, v1, 0x5410);
                sk = __dp4a((int)(w4.y & 0x00FF00FFu), (int)be2, sk);
                ek = __dp4a((int)(w4.y & 0xFF00FF00u), (int)be2, ek);
            }
            {
                int i0 = (int)(w4.z & 0xFFFFu), i1 = (int)(w4.z >> 16);
                unsigned v0 = *(const unsigned short*)&s_be[i0];
                unsigned v1 = *(const unsigned short*)&s_be[i1];
                unsigned be2 = __byte_perm(v0, v1, 0x5410);
                sk = __dp4a((int)(w4.w & 0x00FF00FFu), (int)be2, sk);
                ek = __dp4a((int)(w4.w & 0xFF00FF00u), (int)be2, ek);
            }
        }
        aS += bkj * sk;
        aE += ekj * ek;
    }
    #pragma unroll
    for (int o = 16; o > 0; o >>= 1) {
        aS += __shfl_down_sync(0xFFFFFFFFu, aS, o);
        aE += __shfl_down_sync(0xFFFFFFFFu, aE, o);
    }
    if (lane == 0) { redS[wid] = aS; redE[wid] = aE; }
    __syncthreads();
    if (tid == 0) {
        long long s = 0, t = 0;
        #pragma unroll
        for (int w = 0; w < 8; w++) { s += redS[w]; t += redE[w]; }
        atomicAdd(&g_triS, (unsigned long long)s);
        atomicAdd(&g_triE, (unsigned long long)t);
        atomicAdd(&g_TA, (unsigned long long)((long long)g_colEf[j] * (long long)g_rowsE[j]));
        __threadfence();
        unsigned prev = atomicAdd(&g_done, 1u);
        if (prev == (unsigned)(NN - 1)) {
            long long triS = (long long)atomicAdd(&g_triS, 0ull);
            long long triE = (long long)atomicAdd(&g_triE, 0ull);
            long long T1 = (long long)atomicAdd(&g_T1, 0ull);
            long long T2 = (long long)atomicAdd(&g_T2, 0ull);
            long long Sv = (long long)atomicAdd(&g_S, 0ull);
            long long TA = (long long)atomicAdd(&g_TA, 0ull);
            long long TB = (long long)atomicAdd(&g_TB, 0ull);
            long long nD = (long long)atomicAdd(&g_nD, 0);
            // tr(A^3)  = tr(B^3) - 3*T1 + 3*S*T2 - S^3
            // tr(|A|^3)= tr(E^3) + 3*TA + 3*|D|*TB + |D|^3
            long long tr3  = triS - 3 * T1 + 3 * Sv * T2 - Sv * Sv * Sv;
            long long tr3a = triE + 3 * TA + 3 * nD * TB + nD * nD * nD;
            out[out_size - 1] = (float)(0.5 * (1.0 + (double)tr3 / (double)tr3a));
        }
    }
}

// ---------------- launch ----------------
extern "C" void kernel_launch(void* const* d_in, const int* in_sizes, int n_in,
                              void* d_out, int out_size) {
    const float* ori = (const float*)d_in[0];
    const float* cp  = (const float*)d_in[1];
    const float* u   = (const float*)d_in[2];
    float* out = (float*)d_out;

    k_fuse<<<NTRI, dim3(8, 32)>>>(ori, cp, u, out);

    cudaLaunchAttribute attr[1];
    attr[0].id = cudaLaunchAttributeProgrammaticStreamSerialization;
    attr[0].val.programmaticStreamSerializationAllowed = 1;

    {
        cudaLaunchConfig_t cfg = {};
        cfg.gridDim = dim3(NN);
        cfg.blockDim = dim3(256);
        cfg.attrs = attr;
        cfg.numAttrs = 1;
        cudaLaunchKernelEx(&cfg, k_lists);
    }
    {
        cudaLaunchConfig_t cfg = {};
        cfg.gridDim = dim3(NN);
        cfg.blockDim = dim3(256);
        cfg.attrs = attr;
        cfg.numAttrs = 1;
        cudaLaunchKernelEx(&cfg, k_tri, out, out_size);
    }
}